// round 17
// baseline (speedup 1.0000x reference)
#include <cuda_runtime.h>
#include <cstdint>

#define Bz    4
#define Cc    64
#define Hh    64
#define Ww    64
#define HW    4096
#define CHW   (Cc*HW)
#define PATCH 9
#define CHUNK 16
#define NCH   (Cc/CHUNK)            // 4
#define PROW  72                    // padded row length
#define CROWS 9                     // f2 rows per tile (dy = row)
#define F2C   (CROWS*PROW)          // 648 floats per staged channel
#define F2BUF (CHUNK*F2C)           // 10368 floats
#define F1BUF (CHUNK*Ww)            // 1024 floats
#define SMEM_FLOATS (2*(F2BUF+F1BUF))  // 22784
#define SMEM_BYTES  (SMEM_FLOATS*4)    // 91136
#define NTHR  288                   // 9 warps (warp = dy)
#define NARRIVE 32                  // 16 f2 + 16 f1 copiers
#define PSIZE (PROW*PROW)           // 5184
#define PAD_BLOCKS 1296             // Bz*Cc*72*18 / 256
#define NORM_BLOCKS 64              // 16384 threads
#define AUX_BLOCKS (PAD_BLOCKS + NORM_BLOCKS)

typedef unsigned long long u64;
union f4u { float4 f; ulonglong2 u; };

// scratch
__device__ float g_inv1[Bz][HW];
__device__ float g_inv2p[Bz][72][72];     // padded inverse norms of f2 (halo=1)
__device__ float g_f2p[Bz][Cc][72][72];   // padded RAW f2 (zero halos)

__device__ __forceinline__ uint32_t smem_u32(const void* p) {
    uint32_t a;
    asm("{ .reg .u64 t; cvta.to.shared.u64 t, %1; cvt.u32.u64 %0, t; }" : "=r"(a) : "l"(p));
    return a;
}
__device__ __forceinline__ void bulk_g2s(uint32_t dst, const float* src, uint32_t bytes,
                                         uint32_t mbar) {
    asm volatile("cp.async.bulk.shared::cta.global.mbarrier::complete_tx::bytes "
                 "[%0], [%1], %2, [%3];"
                 :: "r"(dst), "l"(src), "r"(bytes), "r"(mbar) : "memory");
}
__device__ __forceinline__ void mbar_init(uint32_t mbar, uint32_t cnt) {
    asm volatile("mbarrier.init.shared.b64 [%0], %1;" :: "r"(mbar), "r"(cnt) : "memory");
}
__device__ __forceinline__ void mbar_arrive_tx(uint32_t mbar, uint32_t tx) {
    asm volatile("mbarrier.arrive.expect_tx.shared.b64 _, [%0], %1;"
                 :: "r"(mbar), "r"(tx) : "memory");
}
__device__ __forceinline__ void mbar_wait(uint32_t mbar, uint32_t parity) {
    uint32_t done;
    asm volatile("{\n\t.reg .pred p;\n\t"
                 "mbarrier.try_wait.parity.acquire.cta.shared::cta.b64 p, [%1], %2;\n\t"
                 "selp.b32 %0, 1, 0, p;\n\t}"
                 : "=r"(done) : "r"(mbar), "r"(parity) : "memory");
    if (!done) {
        asm volatile("{\n\t.reg .pred P1;\n\t"
                     "WL_%=:\n\t"
                     "mbarrier.try_wait.parity.acquire.cta.shared::cta.b64 P1, [%0], %1, 0x989680;\n\t"
                     "@P1 bra.uni WD_%=;\n\t"
                     "bra.uni WL_%=;\n\t"
                     "WD_%=:\n\t}"
                     :: "r"(mbar), "r"(parity) : "memory");
    }
}
__device__ __forceinline__ u64 pk(float lo, float hi) {
    u64 r; asm("mov.b64 %0, {%1, %2};" : "=l"(r) : "f"(lo), "f"(hi)); return r;
}
__device__ __forceinline__ void fma2(u64& d, u64 a, u64 b) {
    asm("fma.rn.f32x2 %0, %1, %2, %0;" : "+l"(d) : "l"(a), "l"(b));
}
__device__ __forceinline__ void unpk(u64 p, float& lo, float& hi) {
    asm("mov.b64 {%0, %1}, %2;" : "=f"(lo), "=f"(hi) : "l"(p));
}

// ---------------------------------------------------------------------------
// Kernel 1 (fused aux, R16 — measured ~1us):
//   blocks [0, 1296): pad raw f2 into g_f2p (zero halos) + write inv2p halo.
//   blocks [1296, 1360): inverse L2 norms, coalesced lane layout,
//     32 channels/thread, shfl_xor(16) combine.
// ---------------------------------------------------------------------------
__global__ void aux_kernel(const float* __restrict__ f1,
                           const float* __restrict__ f2) {
    if (blockIdx.x < PAD_BLOCKS) {
        int idx = blockIdx.x * 256 + threadIdx.x;
        int xq  = idx % 18;
        int t   = idx / 18;
        int r   = t % 72;  t /= 72;
        int c   = t & 63;
        int b   = t >> 6;
        int y   = r - 4;
        float4 val = make_float4(0.f, 0.f, 0.f, 0.f);
        if (y >= 0 && y < Hh && xq >= 1 && xq <= 16) {
            val = __ldg((const float4*)(f2 + (b * Cc + c) * HW + y * Ww + (xq - 1) * 4));
        }
        *(float4*)&g_f2p[b][c][r][xq * 4] = val;

        if (idx < Bz * 72 * 72) {
            int bb = idx / 5184;
            int rc = idx - bb * 5184;
            int rr = rc / 72, cc = rc - rr * 72;
            if (rr < 4 || rr >= 68 || cc < 4 || cc >= 68)
                g_inv2p[bb][rr][cc] = 1.0f;
        }
    } else {
        int j      = (blockIdx.x - PAD_BLOCKS) * 256 + threadIdx.x;  // 0..16383
        int quadlo = j & 15;
        int cg     = (j >> 4) & 1;
        int quadhi = (j >> 5) & 63;
        int b      = (j >> 11) & 3;
        int feat   = (j >> 13) & 1;
        int quad   = quadhi * 16 + quadlo;
        const float* src = (feat ? f2 : f1) + b * CHW + quad * 4 + cg * 32 * HW;

        float4 s = make_float4(0.f, 0.f, 0.f, 0.f);
#pragma unroll
        for (int i = 0; i < 32; ++i) {
            float4 v = __ldg((const float4*)(src + i * HW));
            s.x += v.x * v.x; s.y += v.y * v.y; s.z += v.z * v.z; s.w += v.w * v.w;
        }
        s.x += __shfl_xor_sync(0xffffffffu, s.x, 16);
        s.y += __shfl_xor_sync(0xffffffffu, s.y, 16);
        s.z += __shfl_xor_sync(0xffffffffu, s.z, 16);
        s.w += __shfl_xor_sync(0xffffffffu, s.w, 16);

        if (cg == 0) {
            float4 r;
            r.x = rsqrtf(s.x + 1e-6f); r.y = rsqrtf(s.y + 1e-6f);
            r.z = rsqrtf(s.z + 1e-6f); r.w = rsqrtf(s.w + 1e-6f);
            int y = quad >> 4, x = (quad & 15) << 2;
            if (feat == 0) *(float4*)&g_inv1[b][quad * 4] = r;
            else           *(float4*)&g_inv2p[b][y + 4][x + 4] = r;
        }
    }
}

// ---------------------------------------------------------------------------
// Kernel 2 (R13 corr — measured 13.3us):
//   grid = [b:4][y:64] = 256 CTAs, 288 threads (9 warps = 9 dy).
//   lane = (ch:1)(xq:4): 4 px of row y, half the channels, all 9 dx.
//   Staging: 16 contiguous 2592B f2-channel copies + 16x256B f1 copies per
//   chunk from the padded scratch (no halo handling). Double buffered.
//   27-slot FFMA2 inner loop, shfl-xor(16) channel combine.
// ---------------------------------------------------------------------------
__global__ __launch_bounds__(NTHR, 2)
void corr_kernel(const float* __restrict__ f1, float* __restrict__ out) {
    extern __shared__ float smem[];
    __shared__ u64 s_mbar[2];

    float* s_f2 = smem;                  // [2][CHUNK][CROWS][PROW]
    float* s_f1 = smem + 2 * F2BUF;      // [2][CHUNK][Ww]
    const uint32_t s2 = smem_u32(s_f2);
    const uint32_t s1 = smem_u32(s_f1);
    const uint32_t mb0 = smem_u32(&s_mbar[0]);
    const uint32_t mb1 = smem_u32(&s_mbar[1]);

    const int b    = blockIdx.x >> 6;
    const int y    = blockIdx.x & 63;
    const int tid  = threadIdx.x;
    const int dy   = tid >> 5;                 // warp = dy (0..8)
    const int lane = tid & 31;
    const int ch   = lane >> 4;                // channel parity
    const int xq   = lane & 15;                // x quad (0..15)
    const int x0   = xq << 2;

    const float* f2base = &g_f2p[b][0][y][0];  // padded rows y..y+8
    const float* f1base = f1 + b * CHW + y * Ww;

    if (tid == 0) { mbar_init(mb0, NARRIVE); mbar_init(mb1, NARRIVE); }
    __syncthreads();

    auto stage = [&](int c0, int sel) {
        uint32_t mb = sel ? mb1 : mb0;
        if (tid < CHUNK) {                     // 16 f2-channel copiers, 2592B
            mbar_arrive_tx(mb, F2C * 4);
            bulk_g2s(s2 + (uint32_t)((sel * F2BUF + tid * F2C) * 4),
                     f2base + (c0 + tid) * PSIZE, F2C * 4, mb);
        } else if (tid < 2 * CHUNK) {          // 16 f1 copiers, 256B
            int c = tid - CHUNK;
            mbar_arrive_tx(mb, Ww * 4);
            bulk_g2s(s1 + (uint32_t)((sel * F1BUF + c * Ww) * 4),
                     f1base + (c0 + c) * HW, Ww * 4, mb);
        }
    };

    u64 eacc[5][2];
    u64 macc[4];
    float s0a[4], s3a[4];
#pragma unroll
    for (int e = 0; e < 5; ++e) { eacc[e][0] = 0ull; eacc[e][1] = 0ull; }
#pragma unroll
    for (int o = 0; o < 4; ++o) { macc[o] = 0ull; s0a[o] = 0.f; s3a[o] = 0.f; }

    stage(0, 0);
    stage(CHUNK, 1);

#pragma unroll 1
    for (int k = 0; k < NCH; ++k) {
        mbar_wait(k & 1 ? mb1 : mb0, (k >> 1) & 1);

        const float* sbuf = s_f2 + (k & 1) * F2BUF + dy * PROW + x0;
        const float* abuf = s_f1 + (k & 1) * F1BUF + x0;
#pragma unroll
        for (int i = 0; i < CHUNK / 2; ++i) {
            const int c = (i << 1) + ch;
            const float* s = sbuf + c * F2C;
            f4u v0, v1, v2, af;
            v0.f = *(const float4*)(s);
            v1.f = *(const float4*)(s + 4);
            v2.f = *(const float4*)(s + 8);
            af.f = *(const float4*)(abuf + c * Ww);

            const u64 a01 = af.u.x;
            const u64 a23 = af.u.y;
            const u64 am  = pk(af.f.y, af.f.z);     // the ONE pack

            fma2(eacc[0][0], a01, v0.u.x); fma2(eacc[0][1], a23, v0.u.y);
            fma2(eacc[1][0], a01, v0.u.y); fma2(eacc[1][1], a23, v1.u.x);
            fma2(eacc[2][0], a01, v1.u.x); fma2(eacc[2][1], a23, v1.u.y);
            fma2(eacc[3][0], a01, v1.u.y); fma2(eacc[3][1], a23, v2.u.x);
            fma2(eacc[4][0], a01, v2.u.x); fma2(eacc[4][1], a23, v2.u.y);

            fma2(macc[0], am, v0.u.y);
            fma2(macc[1], am, v1.u.x);
            fma2(macc[2], am, v1.u.y);
            fma2(macc[3], am, v2.u.x);
            s0a[0] = fmaf(af.f.x, v0.f.y, s0a[0]);
            s0a[1] = fmaf(af.f.x, v0.f.w, s0a[1]);
            s0a[2] = fmaf(af.f.x, v1.f.y, s0a[2]);
            s0a[3] = fmaf(af.f.x, v1.f.w, s0a[3]);
            s3a[0] = fmaf(af.f.w, v1.f.x, s3a[0]);
            s3a[1] = fmaf(af.f.w, v1.f.z, s3a[1]);
            s3a[2] = fmaf(af.f.w, v2.f.x, s3a[2]);
            s3a[3] = fmaf(af.f.w, v2.f.z, s3a[3]);
        }
        if (k + 2 < NCH) {
            __syncthreads();
            stage((k + 2) * CHUNK, k & 1);
        }
    }

    // ---- assemble per-dx results
    float a[PATCH][4];
#pragma unroll
    for (int e = 0; e < 5; ++e) {
        unpk(eacc[e][0], a[2 * e][0], a[2 * e][1]);
        unpk(eacc[e][1], a[2 * e][2], a[2 * e][3]);
    }
#pragma unroll
    for (int o = 0; o < 4; ++o) {
        a[2 * o + 1][0] = s0a[o];
        unpk(macc[o], a[2 * o + 1][1], a[2 * o + 1][2]);
        a[2 * o + 1][3] = s3a[o];
    }

    // ---- combine channel halves in-warp (partner lane = xor 16)
#pragma unroll
    for (int d = 0; d < PATCH; ++d)
#pragma unroll
        for (int j = 0; j < 4; ++j)
            a[d][j] += __shfl_xor_sync(0xffffffffu, a[d][j], 16);

    if (ch == 0) {
        float4 iv1 = *(const float4*)(&g_inv1[b][y * Ww + x0]);
        float e[12];
        *(float4*)&e[0] = *(const float4*)(&g_inv2p[b][y + dy][x0]);
        *(float4*)&e[4] = *(const float4*)(&g_inv2p[b][y + dy][x0 + 4]);
        *(float4*)&e[8] = *(const float4*)(&g_inv2p[b][y + dy][x0 + 8]);

        float* op = out + (size_t)(b * 81 + dy * PATCH) * HW + y * Ww + x0;
#pragma unroll
        for (int d = 0; d < PATCH; ++d) {
            float4 o;
            o.x = fmaxf(a[d][0] * iv1.x * e[d + 0], 0.f);
            o.y = fmaxf(a[d][1] * iv1.y * e[d + 1], 0.f);
            o.z = fmaxf(a[d][2] * iv1.z * e[d + 2], 0.f);
            o.w = fmaxf(a[d][3] * iv1.w * e[d + 3], 0.f);
            *(float4*)(op + d * HW) = o;
        }
    }
}

// ---------------------------------------------------------------------------
extern "C" void kernel_launch(void* const* d_in, const int* in_sizes, int n_in,
                              void* d_out, int out_size) {
    const float* f1 = (const float*)d_in[0];
    const float* f2 = (const float*)d_in[1];
    float* out = (float*)d_out;

    cudaFuncSetAttribute(corr_kernel,
                         cudaFuncAttributeMaxDynamicSharedMemorySize, SMEM_BYTES);

    aux_kernel<<<AUX_BLOCKS, 256>>>(f1, f2);
    corr_kernel<<<Bz * Hh, NTHR, SMEM_BYTES>>>(f1, out);
}